// round 14
// baseline (speedup 1.0000x reference)
#include <cuda_runtime.h>
#include <cuda_fp16.h>
#include <cstdlib>

__attribute__((constructor))
static void hx_set_eager_module_loading() {
    setenv("CUDA_MODULE_LOADING", "EAGER", 1);
}

#define BSZ 4
#define BC  128
#define HH  512
#define LL  8000
#define LT  32
#define NT1 64   // k1 l-tile
#define NT5 64   // k5 l-tile

// ---------------- scratch (static device arrays; ~66.3 MB total) --------------
__device__ __half g_h [(size_t)BSZ * HH * LL];  // post conv1x1+prelu, [b][h][l]
__device__ __half g_g [(size_t)BSZ * HH * LL];  // post dwconv+prelu RAW, [b][h][l]
__device__ float2 g_s1[BSZ * LL];               // cLN1 stats (in-place scan)
__device__ float2 g_s2[BSZ * LL];               // cLN2 stats
__device__ float  g_rs[256];                    // rowsums of [Wout; Wskip]
__device__ __half g_w1h[512 * 128];             // W1 fp16
__device__ __half g_wh [256 * 512];             // [Wout; Wskip] fp16

// ---------------------------------------------------------------------------
// helpers
// ---------------------------------------------------------------------------
__device__ __forceinline__ void mma16816(
    float c[4], unsigned a0, unsigned a1, unsigned a2, unsigned a3,
    unsigned b0, unsigned b1)
{
    asm volatile(
        "mma.sync.aligned.m16n8k16.row.col.f32.f16.f16.f32 "
        "{%0,%1,%2,%3}, {%4,%5,%6,%7}, {%8,%9}, {%0,%1,%2,%3};"
        : "+f"(c[0]), "+f"(c[1]), "+f"(c[2]), "+f"(c[3])
        : "r"(a0), "r"(a1), "r"(a2), "r"(a3), "r"(b0), "r"(b1));
}

__device__ __forceinline__ void cp_async16(void* dst_smem, const void* src) {
    unsigned d = (unsigned)__cvta_generic_to_shared(dst_smem);
    asm volatile("cp.async.cg.shared.global [%0], [%1], 16;" :: "r"(d), "l"(src));
}
__device__ __forceinline__ void cp_commit() {
    asm volatile("cp.async.commit_group;");
}
__device__ __forceinline__ void cp_wait_all() {
    asm volatile("cp.async.wait_group 0;");
}

__device__ __forceinline__ void ldsm_x4(
    unsigned& r0, unsigned& r1, unsigned& r2, unsigned& r3, const __half* p)
{
    unsigned a = (unsigned)__cvta_generic_to_shared(p);
    asm volatile("ldmatrix.sync.aligned.m8n8.x4.shared.b16 {%0,%1,%2,%3}, [%4];"
        : "=r"(r0), "=r"(r1), "=r"(r2), "=r"(r3) : "r"(a));
}
__device__ __forceinline__ void ldsm_x2_trans(
    unsigned& r0, unsigned& r1, const __half* p)
{
    unsigned a = (unsigned)__cvta_generic_to_shared(p);
    asm volatile("ldmatrix.sync.aligned.m8n8.x2.trans.shared.b16 {%0,%1}, [%2];"
        : "=r"(r0), "=r"(r1) : "r"(a));
}

// ---------------------------------------------------------------------------
// KPREP: one-time fp16 weight conversion + rowsums. (unchanged)
// ---------------------------------------------------------------------------
__global__ __launch_bounds__(128) void kprep(
    const float* __restrict__ W1, const float* __restrict__ Wout,
    const float* __restrict__ Wskip)
{
    const int r = blockIdx.x;
    const int t = threadIdx.x;
    __shared__ float red[4];

    const float* src = (r < 128) ? (Wout + (size_t)r * HH)
                                 : (Wskip + (size_t)(r - 128) * HH);
    float s = 0.f;
    {
        float4 v = *reinterpret_cast<const float4*>(src + t * 4);
        __half2 h0 = __floats2half2_rn(v.x, v.y);
        __half2 h1 = __floats2half2_rn(v.z, v.w);
        *reinterpret_cast<__half2*>(&g_wh[(size_t)r * HH + t * 4])     = h0;
        *reinterpret_cast<__half2*>(&g_wh[(size_t)r * HH + t * 4 + 2]) = h1;
        s = v.x + v.y + v.z + v.w;
    }
#pragma unroll
    for (int d = 16; d > 0; d >>= 1) s += __shfl_xor_sync(0xffffffffu, s, d);
    if ((t & 31) == 0) red[t >> 5] = s;
    __syncthreads();
    if (t == 0) g_rs[r] = red[0] + red[1] + red[2] + red[3];

    if (t < 64) {
        int row = r * 2 + (t >> 5);
        int f = t & 31;
        float4 v = *reinterpret_cast<const float4*>(W1 + (size_t)row * BC + f * 4);
        __half2 h0 = __floats2half2_rn(v.x, v.y);
        __half2 h1 = __floats2half2_rn(v.z, v.w);
        *reinterpret_cast<__half2*>(&g_w1h[(size_t)row * BC + f * 4])     = h0;
        *reinterpret_cast<__half2*>(&g_w1h[(size_t)row * BC + f * 4 + 2]) = h1;
    }
}

// ---------------------------------------------------------------------------
// K1 (tensor core): h = prelu(W1 @ x + b1) -> fp16. (unchanged)
// ---------------------------------------------------------------------------
#define K1_SMEM (512 * 136 * 2 + NT1 * 136 * 2 + 16 * 32 * 8)

__global__ __launch_bounds__(512) void k1_tc(
    const float* __restrict__ x, const float* __restrict__ b1,
    const float* __restrict__ a1p)
{
    extern __shared__ char sm1[];
    __half (*W1s)[136] = reinterpret_cast<__half(*)[136]>(sm1);
    __half (*Xsh)[136] = reinterpret_cast<__half(*)[136]>(sm1 + 512 * 136 * 2);
    float2 (*red_s)[32] =
        reinterpret_cast<float2(*)[32]>(sm1 + 512 * 136 * 2 + NT1 * 136 * 2);

    const int b   = blockIdx.y;
    const int l0  = blockIdx.x * NT1;
    const int tid = threadIdx.x;
    const float a1 = __ldg(a1p);

    for (int i = tid; i < 512 * 16; i += 512) {
        int row = i >> 4, seg = i & 15;
        uint4 u = *reinterpret_cast<const uint4*>(g_w1h + (size_t)row * BC + seg * 8);
        *reinterpret_cast<uint4*>(&W1s[row][seg * 8]) = u;
    }

    {
        int ch = tid >> 2, cseg = tid & 3;
        const float* xp = x + ((size_t)b * BC + ch) * LL + l0 + cseg * 16;
#pragma unroll
        for (int f = 0; f < 4; f++) {
            float4 v = *reinterpret_cast<const float4*>(xp + f * 4);
            int c = cseg * 16 + f * 4;
            Xsh[c + 0][ch] = __float2half_rn(v.x);
            Xsh[c + 1][ch] = __float2half_rn(v.y);
            Xsh[c + 2][ch] = __float2half_rn(v.z);
            Xsh[c + 3][ch] = __float2half_rn(v.w);
        }
    }
    __syncthreads();

    const int warp = tid >> 5, lane = tid & 31;
    const int wm = warp >> 1, wn = warp & 1;
    const int gq = lane >> 2, tc = lane & 3;

    float acc[4][4][4];
#pragma unroll
    for (int mt = 0; mt < 4; mt++)
#pragma unroll
        for (int nt = 0; nt < 4; nt++)
#pragma unroll
            for (int i = 0; i < 4; i++) acc[mt][nt][i] = 0.f;

#pragma unroll
    for (int kk = 0; kk < 128; kk += 16) {
        unsigned a[4][4];
#pragma unroll
        for (int mt = 0; mt < 4; mt++) {
            int r = wm * 64 + mt * 16 + gq;
            int k = kk + tc * 2;
            a[mt][0] = *reinterpret_cast<unsigned*>(&W1s[r][k]);
            a[mt][1] = *reinterpret_cast<unsigned*>(&W1s[r + 8][k]);
            a[mt][2] = *reinterpret_cast<unsigned*>(&W1s[r][k + 8]);
            a[mt][3] = *reinterpret_cast<unsigned*>(&W1s[r + 8][k + 8]);
        }
        unsigned bb[4][2];
#pragma unroll
        for (int nt = 0; nt < 4; nt++) {
            int n = wn * 32 + nt * 8 + gq;
            bb[nt][0] = *reinterpret_cast<unsigned*>(&Xsh[n][kk + tc * 2]);
            bb[nt][1] = *reinterpret_cast<unsigned*>(&Xsh[n][kk + tc * 2 + 8]);
        }
#pragma unroll
        for (int mt = 0; mt < 4; mt++)
#pragma unroll
            for (int nt = 0; nt < 4; nt++)
                mma16816(acc[mt][nt], a[mt][0], a[mt][1], a[mt][2], a[mt][3],
                         bb[nt][0], bb[nt][1]);
    }

    float ss[8], qq[8];
#pragma unroll
    for (int i = 0; i < 8; i++) { ss[i] = 0.f; qq[i] = 0.f; }

#pragma unroll
    for (int mt = 0; mt < 4; mt++) {
#pragma unroll
        for (int hf = 0; hf < 2; hf++) {
            int row = wm * 64 + mt * 16 + gq + hf * 8;
            float bbv = __ldg(b1 + row);
            __half* hrow = g_h + ((size_t)b * HH + row) * LL + l0 + wn * 32;
#pragma unroll
            for (int nt = 0; nt < 4; nt++) {
                float v0 = acc[mt][nt][hf * 2 + 0] + bbv;
                v0 = (v0 >= 0.f) ? v0 : a1 * v0;
                float v1 = acc[mt][nt][hf * 2 + 1] + bbv;
                v1 = (v1 >= 0.f) ? v1 : a1 * v1;
                __half2 hx = __floats2half2_rn(v0, v1);
                *reinterpret_cast<__half2*>(hrow + nt * 8 + tc * 2) = hx;
                float2 vr = __half22float2(hx);
                ss[nt * 2 + 0] += vr.x; qq[nt * 2 + 0] += vr.x * vr.x;
                ss[nt * 2 + 1] += vr.y; qq[nt * 2 + 1] += vr.y * vr.y;
            }
        }
    }
#pragma unroll
    for (int m = 4; m < 32; m <<= 1) {
#pragma unroll
        for (int i = 0; i < 8; i++) {
            ss[i] += __shfl_xor_sync(0xffffffffu, ss[i], m);
            qq[i] += __shfl_xor_sync(0xffffffffu, qq[i], m);
        }
    }
    if (lane < 4) {
#pragma unroll
        for (int nt = 0; nt < 4; nt++) {
            red_s[warp][nt * 8 + tc * 2 + 0] = make_float2(ss[nt * 2 + 0], qq[nt * 2 + 0]);
            red_s[warp][nt * 8 + tc * 2 + 1] = make_float2(ss[nt * 2 + 1], qq[nt * 2 + 1]);
        }
    }
    __syncthreads();
    if (tid < NT1) {
        int wn2 = tid >> 5, c = tid & 31;
        float cs = 0.f, cq = 0.f;
#pragma unroll
        for (int w = 0; w < 8; w++) {
            float2 v = red_s[w * 2 + wn2][c];
            cs += v.x; cq += v.y;
        }
        g_s1[b * LL + l0 + tid] = make_float2(cs, cq);
    }
}

// ---------------------------------------------------------------------------
// Scan (IN PLACE)  (unchanged)
// ---------------------------------------------------------------------------
__global__ __launch_bounds__(1024) void kscan(int which)
{
    float2* io = (which ? g_s2 : g_s1) + blockIdx.x * LL;
    const int t = threadIdx.x;
    const int lane = t & 31, w = t >> 5;

    float s = 0.f, q = 0.f;
    float ls[8], lq[8];
    const int base = t * 8;
#pragma unroll
    for (int i = 0; i < 8; i++) {
        int l = base + i;
        float2 v = (l < LL) ? io[l] : make_float2(0.f, 0.f);
        s += v.x; q += v.y; ls[i] = s; lq[i] = q;
    }
    float ts = s, tq = q;
#pragma unroll
    for (int d = 1; d < 32; d <<= 1) {
        float us = __shfl_up_sync(0xffffffffu, ts, d);
        float uq = __shfl_up_sync(0xffffffffu, tq, d);
        if (lane >= d) { ts += us; tq += uq; }
    }
    __shared__ float ws[32], wq[32];
    if (lane == 31) { ws[w] = ts; wq[w] = tq; }
    __syncthreads();
    if (w == 0) {
        float as = ws[lane], aq = wq[lane];
#pragma unroll
        for (int d = 1; d < 32; d <<= 1) {
            float us = __shfl_up_sync(0xffffffffu, as, d);
            float uq = __shfl_up_sync(0xffffffffu, aq, d);
            if (lane >= d) { as += us; aq += uq; }
        }
        ws[lane] = as; wq[lane] = aq;
    }
    __syncthreads();
    float offs = ((w > 0) ? ws[w - 1] : 0.f) + (ts - s);
    float offq = ((w > 0) ? wq[w - 1] : 0.f) + (tq - q);
#pragma unroll
    for (int i = 0; i < 8; i++) {
        int l = base + i;
        if (l < LL) {
            float cs = offs + ls[i], cq = offq + lq[i];
            float cnt = 512.0f * (float)(l + 1);
            float mean = cs / cnt;
            float var = fmaxf(cq / cnt - mean * mean, 0.f);
            io[l] = make_float2(mean, rsqrtf(var + 1e-8f));
        }
    }
}

// ---------------------------------------------------------------------------
// K3 v2: occupancy-tuned. __launch_bounds__(256,3) (regs<=85); cLN1 stats
// read from smem (no register cache); uint2 (8B) halo loads.
// ---------------------------------------------------------------------------
__global__ __launch_bounds__(256, 3) void k3_conv(
    const float* __restrict__ dw, const float* __restrict__ db,
    const float* __restrict__ a2p)
{
    __shared__ float2 smi[LT + 8];
    __shared__ float2 red[8][LT];

    const int b  = blockIdx.y;
    const int l0 = blockIdx.x * LT;
    const int tid = threadIdx.x;
    const int hg = tid >> 2, lg = tid & 3;
    const float a2 = __ldg(a2p);

    if (tid < LT + 8) {
        int l = l0 - 4 + tid;
        smi[tid] = (l >= 0 && l < LL) ? g_s1[b * LL + l] : make_float2(0.f, 0.f);
    }
    __syncthreads();

    const float2* mbase = &smi[lg * 8];   // stats for source cols s0..s0+15

    const int s0 = l0 + lg * 8 - 4;
    const bool interior = (s0 >= 0) && (s0 + 16 <= LL);

    float s[8], q[8];
#pragma unroll
    for (int i = 0; i < 8; i++) { s[i] = 0.f; q[i] = 0.f; }

#pragma unroll
    for (int j = 0; j < 8; j++) {
        int h = hg * 8 + j;
        const __half* hp = g_h + ((size_t)b * HH + h) * LL;
        float v[16];
        if (interior) {
            // s0*2 bytes = 16k-8 -> 8B aligned: four uint2 loads
            const uint2* p2 = reinterpret_cast<const uint2*>(hp + s0);
#pragma unroll
            for (int i = 0; i < 4; i++) {
                uint2 u = p2[i];
                float2 f0 = __half22float2(*reinterpret_cast<__half2*>(&u.x));
                float2 f1 = __half22float2(*reinterpret_cast<__half2*>(&u.y));
                v[4 * i + 0] = f0.x; v[4 * i + 1] = f0.y;
                v[4 * i + 2] = f1.x; v[4 * i + 3] = f1.y;
            }
        } else {
#pragma unroll
            for (int i = 0; i < 16; i++) {
                int l = s0 + i;
                v[i] = (l >= 0 && l < LL) ? __half2float(hp[l]) : 0.f;
            }
        }
        float hn[16];
#pragma unroll
        for (int i = 0; i < 16; i++) {
            float2 m = mbase[i];
            hn[i] = (v[i] - m.x) * m.y;
        }

        float d0 = __ldg(dw + h * 3 + 0);
        float d1 = __ldg(dw + h * 3 + 1);
        float d2 = __ldg(dw + h * 3 + 2);
        float dbv = __ldg(db + h);

        __half* gp = g_g + ((size_t)b * HH + h) * LL + l0 + lg * 8;
        union { __half2 h2[4]; uint4 u; } pk;
#pragma unroll
        for (int i = 0; i < 4; i++) {
            float y0 = d0 * hn[2*i]   + d1 * hn[2*i + 4] + d2 * hn[2*i + 8] + dbv;
            y0 = (y0 >= 0.f) ? y0 : a2 * y0;
            float y1 = d0 * hn[2*i+1] + d1 * hn[2*i + 5] + d2 * hn[2*i + 9] + dbv;
            y1 = (y1 >= 0.f) ? y1 : a2 * y1;
            __half2 hx = __floats2half2_rn(y0, y1);
            pk.h2[i] = hx;
            float2 vr = __half22float2(hx);
            s[2*i]   += vr.x; q[2*i]   += vr.x * vr.x;
            s[2*i+1] += vr.y; q[2*i+1] += vr.y * vr.y;
        }
        *reinterpret_cast<uint4*>(gp) = pk.u;
    }

#pragma unroll
    for (int mm = 4; mm < 32; mm <<= 1) {
#pragma unroll
        for (int i = 0; i < 8; i++) {
            s[i] += __shfl_xor_sync(0xffffffffu, s[i], mm);
            q[i] += __shfl_xor_sync(0xffffffffu, q[i], mm);
        }
    }
    int w = tid >> 5, lane = tid & 31;
    if (lane < 4) {
#pragma unroll
        for (int i = 0; i < 8; i++) red[w][lane * 8 + i] = make_float2(s[i], q[i]);
    }
    __syncthreads();
    if (tid < LT) {
        float cs = 0.f, cq = 0.f;
#pragma unroll
        for (int w2 = 0; w2 < 8; w2++) { float2 v = red[w2][tid]; cs += v.x; cq += v.y; }
        g_s2[b * LL + l0 + tid] = make_float2(cs, cq);
    }
}

// ---------------------------------------------------------------------------
// K5 v6 (unchanged from round-13 passing version)
// ---------------------------------------------------------------------------
#define K5_W_ELE (256 * 72)
#define K5_G_ELE (NT5 * 72)
#define K5_SMEM  ((2 * K5_W_ELE + 2 * K5_G_ELE) * 2 + NT5 * 8)

__global__ __launch_bounds__(256) void k5_tc6(
    const float* __restrict__ bout, const float* __restrict__ bskip,
    const float* __restrict__ x, float* __restrict__ out)
{
    extern __shared__ char sm5[];
    __half* Wsm = reinterpret_cast<__half*>(sm5);                    // [2][256 rows][72 k]
    __half* Gsm = Wsm + 2 * K5_W_ELE;                                // [2][64 k][72 n]
    float2* smi2 = reinterpret_cast<float2*>(Gsm + 2 * K5_G_ELE);    // NT5

    const int b   = blockIdx.y;
    const int l0  = blockIdx.x * NT5;
    const int tid = threadIdx.x;

    if (tid < NT5) smi2[tid] = g_s2[b * LL + l0 + tid];

    const int warp = tid >> 5, lane = tid & 31;
    const int wm = warp >> 1, wn = warp & 1;
    const int gq = lane >> 2, tc = lane & 3;

    auto cp_w = [&](int kc, int st) {
        __half* Wst = Wsm + st * K5_W_ELE;
#pragma unroll
        for (int i = 0; i < 8; i++) {
            int idx = i * 256 + tid;
            int row = idx >> 3, seg = idx & 7;
            cp_async16(Wst + row * 72 + seg * 8,
                       g_wh + (size_t)row * HH + kc + seg * 8);
        }
    };
    auto cp_g = [&](int kc, int st) {
        __half* Gst = Gsm + st * K5_G_ELE;
#pragma unroll
        for (int i = 0; i < 2; i++) {
            int idx = i * 256 + tid;
            int row = idx >> 3, seg = idx & 7;
            cp_async16(Gst + row * 72 + seg * 8,
                       g_g + ((size_t)b * HH + kc + row) * LL + l0 + seg * 8);
        }
    };

    float acc[4][4][4];
#pragma unroll
    for (int mt = 0; mt < 4; mt++)
#pragma unroll
        for (int nt = 0; nt < 4; nt++)
#pragma unroll
            for (int i = 0; i < 4; i++) acc[mt][nt][i] = 0.f;

    cp_w(0, 0); cp_g(0, 0); cp_commit();
    cp_wait_all();
    __syncthreads();

    const int a_row = lane & 15;
    const int a_koff = (lane >> 4) << 3;
    const int b_krow = (lane & 7) + (lane & 8);

    for (int s = 0; s < 8; s++) {
        const int p = s & 1;
        if (s < 7) {
            cp_w((s + 1) * 64, p ^ 1);
            cp_g((s + 1) * 64, p ^ 1);
            cp_commit();
        }

        const __half* Wst = Wsm + p * K5_W_ELE;
        const __half* Gst = Gsm + p * K5_G_ELE;
#pragma unroll
        for (int kk = 0; kk < 64; kk += 16) {
            unsigned a[4][4];
#pragma unroll
            for (int mt = 0; mt < 4; mt++) {
                const __half* pa = Wst + (wm * 64 + mt * 16 + a_row) * 72 + kk + a_koff;
                ldsm_x4(a[mt][0], a[mt][1], a[mt][2], a[mt][3], pa);
            }
            unsigned bb[4][2];
#pragma unroll
            for (int nt = 0; nt < 4; nt++) {
                const __half* pb = Gst + (kk + b_krow) * 72 + wn * 32 + nt * 8;
                ldsm_x2_trans(bb[nt][0], bb[nt][1], pb);
            }
#pragma unroll
            for (int mt = 0; mt < 4; mt++)
#pragma unroll
                for (int nt = 0; nt < 4; nt++)
                    mma16816(acc[mt][nt], a[mt][0], a[mt][1], a[mt][2], a[mt][3],
                             bb[nt][0], bb[nt][1]);
        }

        if (s < 7) {
            cp_wait_all();
            __syncthreads();
        }
    }

    const size_t skip_off = (size_t)BSZ * BC * LL;
#pragma unroll
    for (int mt = 0; mt < 4; mt++) {
        int rbase = wm * 64 + mt * 16 + gq;
#pragma unroll
        for (int nt = 0; nt < 4; nt++) {
            int nloc = wn * 32 + nt * 8 + tc * 2;
            int lcol = l0 + nloc;
            float2 ms0 = smi2[nloc];
            float2 ms1 = smi2[nloc + 1];
#pragma unroll
            for (int hf = 0; hf < 2; hf++) {
                int r = rbase + hf * 8;
                float rsv = __ldg(g_rs + r);
                float o0 = acc[mt][nt][hf * 2 + 0] * ms0.y - rsv * ms0.x * ms0.y;
                float o1 = acc[mt][nt][hf * 2 + 1] * ms1.y - rsv * ms1.x * ms1.y;
                if (r < 128) {
                    float bbv = __ldg(bout + r);
                    float2 xv = *reinterpret_cast<const float2*>(
                        x + ((size_t)b * BC + r) * LL + lcol);
                    float2 o = make_float2(o0 + bbv + xv.x, o1 + bbv + xv.y);
                    *reinterpret_cast<float2*>(
                        out + ((size_t)b * BC + r) * LL + lcol) = o;
                } else {
                    int r2 = r - 128;
                    float bbv = __ldg(bskip + r2);
                    float2 o = make_float2(o0 + bbv, o1 + bbv);
                    *reinterpret_cast<float2*>(
                        out + skip_off + ((size_t)b * BC + r2) * LL + lcol) = o;
                }
            }
        }
    }
}

// ---------------------------------------------------------------------------
extern "C" void kernel_launch(void* const* d_in, const int* in_sizes, int n_in,
                              void* d_out, int out_size)
{
    const float* x     = (const float*)d_in[0];
    const float* W1    = (const float*)d_in[1];
    const float* b1    = (const float*)d_in[2];
    const float* dw    = (const float*)d_in[3];
    const float* db    = (const float*)d_in[4];
    const float* Wout  = (const float*)d_in[5];
    const float* bout  = (const float*)d_in[6];
    const float* Wskip = (const float*)d_in[7];
    const float* bskip = (const float*)d_in[8];
    const float* a1    = (const float*)d_in[9];
    const float* a2    = (const float*)d_in[10];
    float* out = (float*)d_out;

    cudaFuncSetAttribute(k1_tc,  cudaFuncAttributeMaxDynamicSharedMemorySize, K1_SMEM);
    cudaFuncSetAttribute(k5_tc6, cudaFuncAttributeMaxDynamicSharedMemorySize, K5_SMEM);

    kprep<<<256, 128>>>(W1, Wout, Wskip);
    dim3 grid1(LL / NT1, BSZ);
    k1_tc<<<grid1, 512, K1_SMEM>>>(x, b1, a1);
    kscan<<<BSZ, 1024>>>(0);
    dim3 grid3(LL / LT, BSZ);
    k3_conv<<<grid3, 256>>>(dw, db, a2);
    kscan<<<BSZ, 1024>>>(1);
    dim3 grid5(LL / NT5, BSZ);
    k5_tc6<<<grid5, 256, K5_SMEM>>>(bout, bskip, x, out);
}

// round 15
// speedup vs baseline: 1.0438x; 1.0438x over previous
#include <cuda_runtime.h>
#include <cuda_fp16.h>
#include <cstdlib>

__attribute__((constructor))
static void hx_set_eager_module_loading() {
    setenv("CUDA_MODULE_LOADING", "EAGER", 1);
}

#define BSZ 4
#define BC  128
#define HH  512
#define LL  8000
#define LT3 64   // k3 l-tile
#define NT1 64   // k1 l-tile
#define NT5 64   // k5 l-tile

// ---------------- scratch (static device arrays; ~66.3 MB total) --------------
__device__ __half g_h [(size_t)BSZ * HH * LL];  // post conv1x1+prelu, [b][h][l]
__device__ __half g_g [(size_t)BSZ * HH * LL];  // post dwconv+prelu RAW, [b][h][l]
__device__ float2 g_s1[BSZ * LL];               // cLN1 stats (in-place scan)
__device__ float2 g_s2[BSZ * LL];               // cLN2 stats
__device__ float  g_rs[256];                    // rowsums of [Wout; Wskip]
__device__ __half g_w1h[512 * 128];             // W1 fp16
__device__ __half g_wh [256 * 512];             // [Wout; Wskip] fp16

// ---------------------------------------------------------------------------
// helpers
// ---------------------------------------------------------------------------
__device__ __forceinline__ void mma16816(
    float c[4], unsigned a0, unsigned a1, unsigned a2, unsigned a3,
    unsigned b0, unsigned b1)
{
    asm volatile(
        "mma.sync.aligned.m16n8k16.row.col.f32.f16.f16.f32 "
        "{%0,%1,%2,%3}, {%4,%5,%6,%7}, {%8,%9}, {%0,%1,%2,%3};"
        : "+f"(c[0]), "+f"(c[1]), "+f"(c[2]), "+f"(c[3])
        : "r"(a0), "r"(a1), "r"(a2), "r"(a3), "r"(b0), "r"(b1));
}

__device__ __forceinline__ void cp_async16(void* dst_smem, const void* src) {
    unsigned d = (unsigned)__cvta_generic_to_shared(dst_smem);
    asm volatile("cp.async.cg.shared.global [%0], [%1], 16;" :: "r"(d), "l"(src));
}
__device__ __forceinline__ void cp_commit() {
    asm volatile("cp.async.commit_group;");
}
__device__ __forceinline__ void cp_wait_all() {
    asm volatile("cp.async.wait_group 0;");
}

__device__ __forceinline__ void ldsm_x4(
    unsigned& r0, unsigned& r1, unsigned& r2, unsigned& r3, const __half* p)
{
    unsigned a = (unsigned)__cvta_generic_to_shared(p);
    asm volatile("ldmatrix.sync.aligned.m8n8.x4.shared.b16 {%0,%1,%2,%3}, [%4];"
        : "=r"(r0), "=r"(r1), "=r"(r2), "=r"(r3) : "r"(a));
}
__device__ __forceinline__ void ldsm_x2_trans(
    unsigned& r0, unsigned& r1, const __half* p)
{
    unsigned a = (unsigned)__cvta_generic_to_shared(p);
    asm volatile("ldmatrix.sync.aligned.m8n8.x2.trans.shared.b16 {%0,%1}, [%2];"
        : "=r"(r0), "=r"(r1) : "r"(a));
}

// ---------------------------------------------------------------------------
// KPREP: one-time fp16 weight conversion + rowsums. (unchanged)
// ---------------------------------------------------------------------------
__global__ __launch_bounds__(128) void kprep(
    const float* __restrict__ W1, const float* __restrict__ Wout,
    const float* __restrict__ Wskip)
{
    const int r = blockIdx.x;
    const int t = threadIdx.x;
    __shared__ float red[4];

    const float* src = (r < 128) ? (Wout + (size_t)r * HH)
                                 : (Wskip + (size_t)(r - 128) * HH);
    float s = 0.f;
    {
        float4 v = *reinterpret_cast<const float4*>(src + t * 4);
        __half2 h0 = __floats2half2_rn(v.x, v.y);
        __half2 h1 = __floats2half2_rn(v.z, v.w);
        *reinterpret_cast<__half2*>(&g_wh[(size_t)r * HH + t * 4])     = h0;
        *reinterpret_cast<__half2*>(&g_wh[(size_t)r * HH + t * 4 + 2]) = h1;
        s = v.x + v.y + v.z + v.w;
    }
#pragma unroll
    for (int d = 16; d > 0; d >>= 1) s += __shfl_xor_sync(0xffffffffu, s, d);
    if ((t & 31) == 0) red[t >> 5] = s;
    __syncthreads();
    if (t == 0) g_rs[r] = red[0] + red[1] + red[2] + red[3];

    if (t < 64) {
        int row = r * 2 + (t >> 5);
        int f = t & 31;
        float4 v = *reinterpret_cast<const float4*>(W1 + (size_t)row * BC + f * 4);
        __half2 h0 = __floats2half2_rn(v.x, v.y);
        __half2 h1 = __floats2half2_rn(v.z, v.w);
        *reinterpret_cast<__half2*>(&g_w1h[(size_t)row * BC + f * 4])     = h0;
        *reinterpret_cast<__half2*>(&g_w1h[(size_t)row * BC + f * 4 + 2]) = h1;
    }
}

// ---------------------------------------------------------------------------
// K1 (tensor core): h = prelu(W1 @ x + b1) -> fp16. (unchanged)
// ---------------------------------------------------------------------------
#define K1_SMEM (512 * 136 * 2 + NT1 * 136 * 2 + 16 * 32 * 8)

__global__ __launch_bounds__(512) void k1_tc(
    const float* __restrict__ x, const float* __restrict__ b1,
    const float* __restrict__ a1p)
{
    extern __shared__ char sm1[];
    __half (*W1s)[136] = reinterpret_cast<__half(*)[136]>(sm1);
    __half (*Xsh)[136] = reinterpret_cast<__half(*)[136]>(sm1 + 512 * 136 * 2);
    float2 (*red_s)[32] =
        reinterpret_cast<float2(*)[32]>(sm1 + 512 * 136 * 2 + NT1 * 136 * 2);

    const int b   = blockIdx.y;
    const int l0  = blockIdx.x * NT1;
    const int tid = threadIdx.x;
    const float a1 = __ldg(a1p);

    for (int i = tid; i < 512 * 16; i += 512) {
        int row = i >> 4, seg = i & 15;
        uint4 u = *reinterpret_cast<const uint4*>(g_w1h + (size_t)row * BC + seg * 8);
        *reinterpret_cast<uint4*>(&W1s[row][seg * 8]) = u;
    }

    {
        int ch = tid >> 2, cseg = tid & 3;
        const float* xp = x + ((size_t)b * BC + ch) * LL + l0 + cseg * 16;
#pragma unroll
        for (int f = 0; f < 4; f++) {
            float4 v = *reinterpret_cast<const float4*>(xp + f * 4);
            int c = cseg * 16 + f * 4;
            Xsh[c + 0][ch] = __float2half_rn(v.x);
            Xsh[c + 1][ch] = __float2half_rn(v.y);
            Xsh[c + 2][ch] = __float2half_rn(v.z);
            Xsh[c + 3][ch] = __float2half_rn(v.w);
        }
    }
    __syncthreads();

    const int warp = tid >> 5, lane = tid & 31;
    const int wm = warp >> 1, wn = warp & 1;
    const int gq = lane >> 2, tc = lane & 3;

    float acc[4][4][4];
#pragma unroll
    for (int mt = 0; mt < 4; mt++)
#pragma unroll
        for (int nt = 0; nt < 4; nt++)
#pragma unroll
            for (int i = 0; i < 4; i++) acc[mt][nt][i] = 0.f;

#pragma unroll
    for (int kk = 0; kk < 128; kk += 16) {
        unsigned a[4][4];
#pragma unroll
        for (int mt = 0; mt < 4; mt++) {
            int r = wm * 64 + mt * 16 + gq;
            int k = kk + tc * 2;
            a[mt][0] = *reinterpret_cast<unsigned*>(&W1s[r][k]);
            a[mt][1] = *reinterpret_cast<unsigned*>(&W1s[r + 8][k]);
            a[mt][2] = *reinterpret_cast<unsigned*>(&W1s[r][k + 8]);
            a[mt][3] = *reinterpret_cast<unsigned*>(&W1s[r + 8][k + 8]);
        }
        unsigned bb[4][2];
#pragma unroll
        for (int nt = 0; nt < 4; nt++) {
            int n = wn * 32 + nt * 8 + gq;
            bb[nt][0] = *reinterpret_cast<unsigned*>(&Xsh[n][kk + tc * 2]);
            bb[nt][1] = *reinterpret_cast<unsigned*>(&Xsh[n][kk + tc * 2 + 8]);
        }
#pragma unroll
        for (int mt = 0; mt < 4; mt++)
#pragma unroll
            for (int nt = 0; nt < 4; nt++)
                mma16816(acc[mt][nt], a[mt][0], a[mt][1], a[mt][2], a[mt][3],
                         bb[nt][0], bb[nt][1]);
    }

    float ss[8], qq[8];
#pragma unroll
    for (int i = 0; i < 8; i++) { ss[i] = 0.f; qq[i] = 0.f; }

#pragma unroll
    for (int mt = 0; mt < 4; mt++) {
#pragma unroll
        for (int hf = 0; hf < 2; hf++) {
            int row = wm * 64 + mt * 16 + gq + hf * 8;
            float bbv = __ldg(b1 + row);
            __half* hrow = g_h + ((size_t)b * HH + row) * LL + l0 + wn * 32;
#pragma unroll
            for (int nt = 0; nt < 4; nt++) {
                float v0 = acc[mt][nt][hf * 2 + 0] + bbv;
                v0 = (v0 >= 0.f) ? v0 : a1 * v0;
                float v1 = acc[mt][nt][hf * 2 + 1] + bbv;
                v1 = (v1 >= 0.f) ? v1 : a1 * v1;
                __half2 hx = __floats2half2_rn(v0, v1);
                *reinterpret_cast<__half2*>(hrow + nt * 8 + tc * 2) = hx;
                float2 vr = __half22float2(hx);
                ss[nt * 2 + 0] += vr.x; qq[nt * 2 + 0] += vr.x * vr.x;
                ss[nt * 2 + 1] += vr.y; qq[nt * 2 + 1] += vr.y * vr.y;
            }
        }
    }
#pragma unroll
    for (int m = 4; m < 32; m <<= 1) {
#pragma unroll
        for (int i = 0; i < 8; i++) {
            ss[i] += __shfl_xor_sync(0xffffffffu, ss[i], m);
            qq[i] += __shfl_xor_sync(0xffffffffu, qq[i], m);
        }
    }
    if (lane < 4) {
#pragma unroll
        for (int nt = 0; nt < 4; nt++) {
            red_s[warp][nt * 8 + tc * 2 + 0] = make_float2(ss[nt * 2 + 0], qq[nt * 2 + 0]);
            red_s[warp][nt * 8 + tc * 2 + 1] = make_float2(ss[nt * 2 + 1], qq[nt * 2 + 1]);
        }
    }
    __syncthreads();
    if (tid < NT1) {
        int wn2 = tid >> 5, c = tid & 31;
        float cs = 0.f, cq = 0.f;
#pragma unroll
        for (int w = 0; w < 8; w++) {
            float2 v = red_s[w * 2 + wn2][c];
            cs += v.x; cq += v.y;
        }
        g_s1[b * LL + l0 + tid] = make_float2(cs, cq);
    }
}

// ---------------------------------------------------------------------------
// Scan (IN PLACE)  (unchanged)
// ---------------------------------------------------------------------------
__global__ __launch_bounds__(1024) void kscan(int which)
{
    float2* io = (which ? g_s2 : g_s1) + blockIdx.x * LL;
    const int t = threadIdx.x;
    const int lane = t & 31, w = t >> 5;

    float s = 0.f, q = 0.f;
    float ls[8], lq[8];
    const int base = t * 8;
#pragma unroll
    for (int i = 0; i < 8; i++) {
        int l = base + i;
        float2 v = (l < LL) ? io[l] : make_float2(0.f, 0.f);
        s += v.x; q += v.y; ls[i] = s; lq[i] = q;
    }
    float ts = s, tq = q;
#pragma unroll
    for (int d = 1; d < 32; d <<= 1) {
        float us = __shfl_up_sync(0xffffffffu, ts, d);
        float uq = __shfl_up_sync(0xffffffffu, tq, d);
        if (lane >= d) { ts += us; tq += uq; }
    }
    __shared__ float ws[32], wq[32];
    if (lane == 31) { ws[w] = ts; wq[w] = tq; }
    __syncthreads();
    if (w == 0) {
        float as = ws[lane], aq = wq[lane];
#pragma unroll
        for (int d = 1; d < 32; d <<= 1) {
            float us = __shfl_up_sync(0xffffffffu, as, d);
            float uq = __shfl_up_sync(0xffffffffu, aq, d);
            if (lane >= d) { as += us; aq += uq; }
        }
        ws[lane] = as; wq[lane] = aq;
    }
    __syncthreads();
    float offs = ((w > 0) ? ws[w - 1] : 0.f) + (ts - s);
    float offq = ((w > 0) ? wq[w - 1] : 0.f) + (tq - q);
#pragma unroll
    for (int i = 0; i < 8; i++) {
        int l = base + i;
        if (l < LL) {
            float cs = offs + ls[i], cq = offq + lq[i];
            float cnt = 512.0f * (float)(l + 1);
            float mean = cs / cnt;
            float var = fmaxf(cq / cnt - mean * mean, 0.f);
            io[l] = make_float2(mean, rsqrtf(var + 1e-8f));
        }
    }
}

// ---------------------------------------------------------------------------
// K3 v3: 512 threads, LT3=64. hg=tid>>3 (8 channels), lg=tid&7 (8-col group).
// Lanes sharing an hg group read ADJACENT 8-col windows -> each LDG.64
// wavefront covers 4 rows x 64B contiguous (was 8 rows x 32B): half the L1
// wavefronts. Stats cached in registers (round-13 proven body).
// ---------------------------------------------------------------------------
__global__ __launch_bounds__(512) void k3_conv(
    const float* __restrict__ dw, const float* __restrict__ db,
    const float* __restrict__ a2p)
{
    __shared__ float2 smi[LT3 + 8];
    __shared__ float2 red[16][LT3];

    const int b  = blockIdx.y;
    const int l0 = blockIdx.x * LT3;
    const int tid = threadIdx.x;
    const int hg = tid >> 3;      // 0..63 -> channels hg*8..+7
    const int lg = tid & 7;       // 0..7  -> cols lg*8..+7
    const float a2 = __ldg(a2p);

    if (tid < LT3 + 8) {
        int l = l0 - 4 + tid;
        smi[tid] = (l >= 0 && l < LL) ? g_s1[b * LL + l] : make_float2(0.f, 0.f);
    }
    __syncthreads();

    float2 m[16];
#pragma unroll
    for (int i = 0; i < 16; i++) m[i] = smi[lg * 8 + i];

    const int s0 = l0 + lg * 8 - 4;
    const bool interior = (s0 >= 0) && (s0 + 16 <= LL);

    float s[8], q[8];
#pragma unroll
    for (int i = 0; i < 8; i++) { s[i] = 0.f; q[i] = 0.f; }

#pragma unroll
    for (int j = 0; j < 8; j++) {
        int h = hg * 8 + j;
        const __half* hp = g_h + ((size_t)b * HH + h) * LL;
        float v[16];
        if (interior) {
            const uint2* p2 = reinterpret_cast<const uint2*>(hp + s0);
#pragma unroll
            for (int i = 0; i < 4; i++) {
                uint2 u = p2[i];
                float2 f0 = __half22float2(*reinterpret_cast<__half2*>(&u.x));
                float2 f1 = __half22float2(*reinterpret_cast<__half2*>(&u.y));
                v[4 * i + 0] = f0.x; v[4 * i + 1] = f0.y;
                v[4 * i + 2] = f1.x; v[4 * i + 3] = f1.y;
            }
        } else {
#pragma unroll
            for (int i = 0; i < 16; i++) {
                int l = s0 + i;
                v[i] = (l >= 0 && l < LL) ? __half2float(hp[l]) : 0.f;
            }
        }
        float hn[16];
#pragma unroll
        for (int i = 0; i < 16; i++) hn[i] = (v[i] - m[i].x) * m[i].y;

        float d0 = __ldg(dw + h * 3 + 0);
        float d1 = __ldg(dw + h * 3 + 1);
        float d2 = __ldg(dw + h * 3 + 2);
        float dbv = __ldg(db + h);

        __half* gp = g_g + ((size_t)b * HH + h) * LL + l0 + lg * 8;
        union { __half2 h2[4]; uint4 u; } pk;
#pragma unroll
        for (int i = 0; i < 4; i++) {
            float y0 = d0 * hn[2*i]   + d1 * hn[2*i + 4] + d2 * hn[2*i + 8] + dbv;
            y0 = (y0 >= 0.f) ? y0 : a2 * y0;
            float y1 = d0 * hn[2*i+1] + d1 * hn[2*i + 5] + d2 * hn[2*i + 9] + dbv;
            y1 = (y1 >= 0.f) ? y1 : a2 * y1;
            __half2 hx = __floats2half2_rn(y0, y1);
            pk.h2[i] = hx;
            float2 vr = __half22float2(hx);
            s[2*i]   += vr.x; q[2*i]   += vr.x * vr.x;
            s[2*i+1] += vr.y; q[2*i+1] += vr.y * vr.y;
        }
        *reinterpret_cast<uint4*>(gp) = pk.u;
    }

    // reduce over the 4 hg-lanes inside the warp (lane bits 3,4)
#pragma unroll
    for (int mm = 8; mm < 32; mm <<= 1) {
#pragma unroll
        for (int i = 0; i < 8; i++) {
            s[i] += __shfl_xor_sync(0xffffffffu, s[i], mm);
            q[i] += __shfl_xor_sync(0xffffffffu, q[i], mm);
        }
    }
    int w = tid >> 5, lane = tid & 31;
    if (lane < 8) {
#pragma unroll
        for (int i = 0; i < 8; i++) red[w][lane * 8 + i] = make_float2(s[i], q[i]);
    }
    __syncthreads();
    if (tid < LT3) {
        float cs = 0.f, cq = 0.f;
#pragma unroll
        for (int w2 = 0; w2 < 16; w2++) { float2 v = red[w2][tid]; cs += v.x; cq += v.y; }
        g_s2[b * LL + l0 + tid] = make_float2(cs, cq);
    }
}

// ---------------------------------------------------------------------------
// K5 v6 (unchanged from round-13 passing version)
// ---------------------------------------------------------------------------
#define K5_W_ELE (256 * 72)
#define K5_G_ELE (NT5 * 72)
#define K5_SMEM  ((2 * K5_W_ELE + 2 * K5_G_ELE) * 2 + NT5 * 8)

__global__ __launch_bounds__(256) void k5_tc6(
    const float* __restrict__ bout, const float* __restrict__ bskip,
    const float* __restrict__ x, float* __restrict__ out)
{
    extern __shared__ char sm5[];
    __half* Wsm = reinterpret_cast<__half*>(sm5);                    // [2][256 rows][72 k]
    __half* Gsm = Wsm + 2 * K5_W_ELE;                                // [2][64 k][72 n]
    float2* smi2 = reinterpret_cast<float2*>(Gsm + 2 * K5_G_ELE);    // NT5

    const int b   = blockIdx.y;
    const int l0  = blockIdx.x * NT5;
    const int tid = threadIdx.x;

    if (tid < NT5) smi2[tid] = g_s2[b * LL + l0 + tid];

    const int warp = tid >> 5, lane = tid & 31;
    const int wm = warp >> 1, wn = warp & 1;
    const int gq = lane >> 2, tc = lane & 3;

    auto cp_w = [&](int kc, int st) {
        __half* Wst = Wsm + st * K5_W_ELE;
#pragma unroll
        for (int i = 0; i < 8; i++) {
            int idx = i * 256 + tid;
            int row = idx >> 3, seg = idx & 7;
            cp_async16(Wst + row * 72 + seg * 8,
                       g_wh + (size_t)row * HH + kc + seg * 8);
        }
    };
    auto cp_g = [&](int kc, int st) {
        __half* Gst = Gsm + st * K5_G_ELE;
#pragma unroll
        for (int i = 0; i < 2; i++) {
            int idx = i * 256 + tid;
            int row = idx >> 3, seg = idx & 7;
            cp_async16(Gst + row * 72 + seg * 8,
                       g_g + ((size_t)b * HH + kc + row) * LL + l0 + seg * 8);
        }
    };

    float acc[4][4][4];
#pragma unroll
    for (int mt = 0; mt < 4; mt++)
#pragma unroll
        for (int nt = 0; nt < 4; nt++)
#pragma unroll
            for (int i = 0; i < 4; i++) acc[mt][nt][i] = 0.f;

    cp_w(0, 0); cp_g(0, 0); cp_commit();
    cp_wait_all();
    __syncthreads();

    const int a_row = lane & 15;
    const int a_koff = (lane >> 4) << 3;
    const int b_krow = (lane & 7) + (lane & 8);

    for (int s = 0; s < 8; s++) {
        const int p = s & 1;
        if (s < 7) {
            cp_w((s + 1) * 64, p ^ 1);
            cp_g((s + 1) * 64, p ^ 1);
            cp_commit();
        }

        const __half* Wst = Wsm + p * K5_W_ELE;
        const __half* Gst = Gsm + p * K5_G_ELE;
#pragma unroll
        for (int kk = 0; kk < 64; kk += 16) {
            unsigned a[4][4];
#pragma unroll
            for (int mt = 0; mt < 4; mt++) {
                const __half* pa = Wst + (wm * 64 + mt * 16 + a_row) * 72 + kk + a_koff;
                ldsm_x4(a[mt][0], a[mt][1], a[mt][2], a[mt][3], pa);
            }
            unsigned bb[4][2];
#pragma unroll
            for (int nt = 0; nt < 4; nt++) {
                const __half* pb = Gst + (kk + b_krow) * 72 + wn * 32 + nt * 8;
                ldsm_x2_trans(bb[nt][0], bb[nt][1], pb);
            }
#pragma unroll
            for (int mt = 0; mt < 4; mt++)
#pragma unroll
                for (int nt = 0; nt < 4; nt++)
                    mma16816(acc[mt][nt], a[mt][0], a[mt][1], a[mt][2], a[mt][3],
                             bb[nt][0], bb[nt][1]);
        }

        if (s < 7) {
            cp_wait_all();
            __syncthreads();
        }
    }

    const size_t skip_off = (size_t)BSZ * BC * LL;
#pragma unroll
    for (int mt = 0; mt < 4; mt++) {
        int rbase = wm * 64 + mt * 16 + gq;
#pragma unroll
        for (int nt = 0; nt < 4; nt++) {
            int nloc = wn * 32 + nt * 8 + tc * 2;
            int lcol = l0 + nloc;
            float2 ms0 = smi2[nloc];
            float2 ms1 = smi2[nloc + 1];
#pragma unroll
            for (int hf = 0; hf < 2; hf++) {
                int r = rbase + hf * 8;
                float rsv = __ldg(g_rs + r);
                float o0 = acc[mt][nt][hf * 2 + 0] * ms0.y - rsv * ms0.x * ms0.y;
                float o1 = acc[mt][nt][hf * 2 + 1] * ms1.y - rsv * ms1.x * ms1.y;
                if (r < 128) {
                    float bbv = __ldg(bout + r);
                    float2 xv = *reinterpret_cast<const float2*>(
                        x + ((size_t)b * BC + r) * LL + lcol);
                    float2 o = make_float2(o0 + bbv + xv.x, o1 + bbv + xv.y);
                    *reinterpret_cast<float2*>(
                        out + ((size_t)b * BC + r) * LL + lcol) = o;
                } else {
                    int r2 = r - 128;
                    float bbv = __ldg(bskip + r2);
                    float2 o = make_float2(o0 + bbv, o1 + bbv);
                    *reinterpret_cast<float2*>(
                        out + skip_off + ((size_t)b * BC + r2) * LL + lcol) = o;
                }
            }
        }
    }
}

// ---------------------------------------------------------------------------
extern "C" void kernel_launch(void* const* d_in, const int* in_sizes, int n_in,
                              void* d_out, int out_size)
{
    const float* x     = (const float*)d_in[0];
    const float* W1    = (const float*)d_in[1];
    const float* b1    = (const float*)d_in[2];
    const float* dw    = (const float*)d_in[3];
    const float* db    = (const float*)d_in[4];
    const float* Wout  = (const float*)d_in[5];
    const float* bout  = (const float*)d_in[6];
    const float* Wskip = (const float*)d_in[7];
    const float* bskip = (const float*)d_in[8];
    const float* a1    = (const float*)d_in[9];
    const float* a2    = (const float*)d_in[10];
    float* out = (float*)d_out;

    cudaFuncSetAttribute(k1_tc,  cudaFuncAttributeMaxDynamicSharedMemorySize, K1_SMEM);
    cudaFuncSetAttribute(k5_tc6, cudaFuncAttributeMaxDynamicSharedMemorySize, K5_SMEM);

    kprep<<<256, 128>>>(W1, Wout, Wskip);
    dim3 grid1(LL / NT1, BSZ);
    k1_tc<<<grid1, 512, K1_SMEM>>>(x, b1, a1);
    kscan<<<BSZ, 1024>>>(0);
    dim3 grid3(LL / LT3, BSZ);
    k3_conv<<<grid3, 512>>>(dw, db, a2);
    kscan<<<BSZ, 1024>>>(1);
    dim3 grid5(LL / NT5, BSZ);
    k5_tc6<<<grid5, 256, K5_SMEM>>>(bout, bskip, x, out);
}